// round 15
// baseline (speedup 1.0000x reference)
#include <cuda_runtime.h>
#include <cuda_bf16.h>
#include <cooperative_groups.h>
#include <cstdint>
#include <cstddef>

namespace cg = cooperative_groups;

// Problem constants (from reference: B=2048, IN=784, H=128, OUT=10, T=100)
#define IN_DIM   784
#define H_DIM    128
#define HH        64      // hidden columns per CTA (cluster of 2 splits H)
#define OUT_DIM   10
#define BETA_F   0.9f
#define ROWS_PER_CLUSTER 28   // 74 clusters * 28 = 2072 >= 2048; 148 CTAs = 1 full wave
#define NWARP     14
#define NTHREADS (NWARP*32)   // 448
#define NJ        25          // ceil(784/32)

#define MAXB 2048
#define MAXT 100

// Spike bitmasks: [T][B][NJ] words, bit b of word j = spike at input j*32+b.
__device__ unsigned g_masks[(size_t)MAXT * MAXB * NJ];   // 20.5 MB scratch

// SMEM: W1 half [784][64] fp32 (200704 B) + W2 [128][10] (5120 B) + spike buf
#define SMEM_BYTES ((IN_DIM*HH + H_DIM*OUT_DIM) * sizeof(float) + 2*ROWS_PER_CLUSTER*2*sizeof(unsigned))

// ---------------------------------------------------------------------------
// Pass 1: Poisson encoding. One CTA per batch row; warp w handles t = w, w+8,…
// Reads 642 MB noise once at full MLP, writes 20.5 MB of ballot masks.
// ---------------------------------------------------------------------------
__global__ void __launch_bounds__(256, 8)
snn_encode_kernel(const float* __restrict__ x,
                  const float* __restrict__ noise,
                  int B, int T)
{
    const int row  = blockIdx.x;
    const int wid  = threadIdx.x >> 5;
    const int lane = threadIdx.x & 31;

    // Per-lane spike probabilities (fp32-exact vs reference: clip(x*0.1, 0, 1))
    float pr[NJ];
#pragma unroll
    for (int j = 0; j < NJ; j++) {
        int i = j * 32 + lane;
        float xv = (i < IN_DIM) ? x[(size_t)row * IN_DIM + i] : -1.0f;
        pr[j] = fminf(fmaxf(__fmul_rn(xv, 0.1f), 0.0f), 1.0f);
    }

    for (int t = wid; t < T; t += 8) {
        const float* np = noise + ((size_t)t * B + row) * IN_DIM;
        float nv[NJ];
#pragma unroll
        for (int j = 0; j < NJ; j++) {
            int i = j * 32 + lane;
            nv[j] = (i < IN_DIM) ? np[i] : 2.0f;   // 2.0 < pr is always false
        }
        unsigned myw = 0;
#pragma unroll
        for (int j = 0; j < NJ; j++) {
            unsigned m = __ballot_sync(0xffffffffu, nv[j] < pr[j]);
            if (lane == j) myw = m;
        }
        if (lane < NJ)
            g_masks[((size_t)t * B + row) * NJ + lane] = myw;
    }
}

// ---------------------------------------------------------------------------
// Pass 2: LIF recurrence. Cluster of 2 CTAs splits H=128; W1 half in smem.
// T-loop consumes only the L2-resident mask words (no noise traffic).
// ---------------------------------------------------------------------------
__global__ void __launch_bounds__(NTHREADS, 1)
snn_cluster_kernel(const float* __restrict__ W1,
                   const float* __restrict__ b1,
                   const float* __restrict__ W2,
                   const float* __restrict__ b2,
                   float* __restrict__ out,
                   int B, int T)
{
    extern __shared__ float smem[];
    float*    W1s = smem;                                  // [784][64]
    float*    W2s = smem + IN_DIM * HH;                    // [128][10]
    unsigned* spb = (unsigned*)(W2s + H_DIM * OUT_DIM);    // [2 parity][28 rows][2 words]

    cg::cluster_group cluster = cg::this_cluster();
    const int rank = (int)cluster.block_rank();            // 0 or 1
    const unsigned* rspb =
        (const unsigned*)cluster.map_shared_rank((void*)spb, rank ^ 1);

    const int tid  = threadIdx.x;
    const int wid  = tid >> 5;
    const int lane = tid & 31;
    const int cid  = blockIdx.x >> 1;

    // Stage W1 half + W2 into shared (read from HBM once per CTA)
    for (int idx = tid; idx < IN_DIM * HH; idx += NTHREADS) {
        int i = idx >> 6;
        int c = idx & 63;
        W1s[idx] = W1[i * H_DIM + rank * HH + c];
    }
    for (int idx = tid; idx < H_DIM * OUT_DIM; idx += NTHREADS)
        W2s[idx] = W2[idx];
    __syncthreads();

    const float b1c0 = b1[rank * HH + 2 * lane];
    const float b1c1 = b1[rank * HH + 2 * lane + 1];
    const float b2v  = (lane < OUT_DIM) ? b2[lane] : 0.0f;

    const int row0 = cid * ROWS_PER_CLUSTER + wid;
    const int row1 = row0 + NWARP;
    const bool v0 = (row0 < B);
    const bool v1 = (row1 < B);

    float mA0 = 0.0f, mA1 = 0.0f;
    float mB0 = 0.0f, mB1 = 0.0f;
    float mem2a = 0.0f, mem2b = 0.0f;
    float cnta = 0.0f, cntb = 0.0f;

    // Layer-1 step: mask-driven sparse W1 gather + LIF + spike-ballot publish.
    auto layer1_row = [&](float& m0, float& m1, int row, int rl, int par, int t) {
        const unsigned* mp = g_masks + ((size_t)t * B + row) * NJ;
        unsigned mw[NJ];
#pragma unroll
        for (int j = 0; j < NJ; j++) mw[j] = mp[j];   // uniform, batched (L2 hits)

        float a0 = 0.0f, a1 = 0.0f;
#pragma unroll
        for (int j = 0; j < NJ; j++) {
            unsigned m = mw[j];
            const float* base = W1s + (j * 32 << 6) + (lane << 1);
            while (m) {
                int bb = __ffs(m) - 1; m &= (m - 1);
                float2 w = *(const float2*)(base + (bb << 6));
                a0 = __fadd_rn(a0, w.x);
                a1 = __fadd_rn(a1, w.y);
            }
        }
        m0 = __fadd_rn(__fadd_rn(__fmul_rn(BETA_F, m0), a0), b1c0);
        m1 = __fadd_rn(__fadd_rn(__fmul_rn(BETA_F, m1), a1), b1c1);
        bool s0 = (m0 >= 1.0f);
        bool s1 = (m1 >= 1.0f);
        if (s0) m0 = 0.0f;
        if (s1) m1 = 0.0f;
        unsigned e = __ballot_sync(0xffffffffu, s0);  // bit l -> local h = 2l
        unsigned o = __ballot_sync(0xffffffffu, s1);  // bit l -> local h = 2l+1
        if (lane == 0) {
            spb[(par * ROWS_PER_CLUSTER + rl) * 2 + 0] = e;
            spb[(par * ROWS_PER_CLUSTER + rl) * 2 + 1] = o;
        }
    };

    // Layer-2 step (rank 0 only, lanes 0..9): gather sp1 halves, LIF, count.
    auto layer2_row = [&](float& m2, float& cnt, int rl, int par) {
        unsigned e0 = spb [(par * ROWS_PER_CLUSTER + rl) * 2 + 0];
        unsigned o0 = spb [(par * ROWS_PER_CLUSTER + rl) * 2 + 1];
        unsigned e1 = rspb[(par * ROWS_PER_CLUSTER + rl) * 2 + 0];
        unsigned o1 = rspb[(par * ROWS_PER_CLUSTER + rl) * 2 + 1];
        float s2 = 0.0f;
        unsigned m;
        m = e0; while (m) { int h =      2*(__ffs(m)-1);     m &= m-1; s2 = __fadd_rn(s2, W2s[h*OUT_DIM + lane]); }
        m = o0; while (m) { int h =      2*(__ffs(m)-1) + 1; m &= m-1; s2 = __fadd_rn(s2, W2s[h*OUT_DIM + lane]); }
        m = e1; while (m) { int h = 64 + 2*(__ffs(m)-1);     m &= m-1; s2 = __fadd_rn(s2, W2s[h*OUT_DIM + lane]); }
        m = o1; while (m) { int h = 64 + 2*(__ffs(m)-1) + 1; m &= m-1; s2 = __fadd_rn(s2, W2s[h*OUT_DIM + lane]); }
        m2 = __fadd_rn(__fadd_rn(__fmul_rn(BETA_F, m2), s2), b2v);
        if (m2 >= 1.0f) { cnt = __fadd_rn(cnt, 1.0f); m2 = 0.0f; }
    };

    for (int t = 0; t < T; t++) {
        const int par = t & 1;
        if (v0) layer1_row(mA0, mA1, row0, wid,         par, t);
        if (v1) layer1_row(mB0, mB1, row1, wid + NWARP, par, t);

        cluster.sync();   // publish sp1 halves across the pair (double-buffered)

        if (rank == 0 && lane < OUT_DIM) {
            if (v0) layer2_row(mem2a, cnta, wid,         par);
            if (v1) layer2_row(mem2b, cntb, wid + NWARP, par);
        }
    }

    if (rank == 0 && lane < OUT_DIM) {
        if (v0) out[(size_t)row0 * OUT_DIM + lane] = cnta;
        if (v1) out[(size_t)row1 * OUT_DIM + lane] = cntb;
    }

    // No CTA may exit while its peer can still read this CTA's SMEM via DSMEM.
    cluster.sync();
}

extern "C" void kernel_launch(void* const* d_in, const int* in_sizes, int n_in,
                              void* d_out, int out_size) {
    const float* x     = (const float*)d_in[0];
    const float* noise = (const float*)d_in[1];
    const float* W1    = (const float*)d_in[2];
    const float* b1    = (const float*)d_in[3];
    const float* W2    = (const float*)d_in[4];
    const float* b2    = (const float*)d_in[5];
    float* out = (float*)d_out;

    const int B = in_sizes[0] / IN_DIM;                                    // 2048
    const int T = (int)((long long)in_sizes[1] / ((long long)B * IN_DIM)); // 100

    // Pass 1: Poisson encoding -> bitmasks (fully parallel, DRAM-bound)
    snn_encode_kernel<<<B, 256>>>(x, noise, B, T);

    // Pass 2: LIF recurrence over L2-resident masks
    const int numClusters = (B + ROWS_PER_CLUSTER - 1) / ROWS_PER_CLUSTER;  // 74

    cudaFuncSetAttribute(snn_cluster_kernel,
                         cudaFuncAttributeMaxDynamicSharedMemorySize,
                         (int)SMEM_BYTES);

    cudaLaunchConfig_t cfg = {};
    cfg.gridDim  = dim3(2 * numClusters, 1, 1);  // 148 CTAs = 74 clusters, one wave
    cfg.blockDim = dim3(NTHREADS, 1, 1);
    cfg.dynamicSmemBytes = SMEM_BYTES;
    cfg.stream = 0;

    cudaLaunchAttribute attrs[1];
    attrs[0].id = cudaLaunchAttributeClusterDimension;
    attrs[0].val.clusterDim.x = 2;
    attrs[0].val.clusterDim.y = 1;
    attrs[0].val.clusterDim.z = 1;
    cfg.attrs = attrs;
    cfg.numAttrs = 1;

    cudaLaunchKernelEx(&cfg, snn_cluster_kernel, W1, b1, W2, b2, out, B, T);
}

// round 16
// speedup vs baseline: 1.0014x; 1.0014x over previous
#include <cuda_runtime.h>
#include <cuda_bf16.h>
#include <cooperative_groups.h>
#include <cstdint>
#include <cstddef>

namespace cg = cooperative_groups;

// Problem constants (from reference: B=2048, IN=784, H=128, OUT=10, T=100)
#define IN_DIM   784
#define H_DIM    128
#define HH        64      // hidden columns per CTA (cluster of 2 splits H)
#define OUT_DIM   10
#define BETA_F   0.9f
#define ROWS_PER_CLUSTER 28   // 74 clusters * 28 = 2072 >= 2048; 148 CTAs = 1 full wave
#define NWARP     14
#define NTHREADS (NWARP*32)   // 448
#define NJ        25          // ceil(784/32)

#define MAXB 2048
#define MAXT 100

// Spike bitmasks: [T][B][NJ] words, bit b of word j = spike at input j*32+b.
__device__ unsigned g_masks[(size_t)MAXT * MAXB * NJ];   // 20.5 MB scratch

// SMEM: W1 half [784][64] fp32 (200704 B) + W2 [128][10] (5120 B) + spike buf
#define SMEM_BYTES ((IN_DIM*HH + H_DIM*OUT_DIM) * sizeof(float) + 2*ROWS_PER_CLUSTER*2*sizeof(unsigned))

// ---------------------------------------------------------------------------
// Pass 1: Poisson encoding. One CTA per batch row; warp w handles t = w, w+8,…
// Reads 642 MB noise once at full MLP, writes 20.5 MB of ballot masks.
// ---------------------------------------------------------------------------
__global__ void __launch_bounds__(256, 8)
snn_encode_kernel(const float* __restrict__ x,
                  const float* __restrict__ noise,
                  int B, int T)
{
    const int row  = blockIdx.x;
    const int wid  = threadIdx.x >> 5;
    const int lane = threadIdx.x & 31;

    // Per-lane spike probabilities (fp32-exact vs reference: clip(x*0.1, 0, 1))
    float pr[NJ];
#pragma unroll
    for (int j = 0; j < NJ; j++) {
        int i = j * 32 + lane;
        float xv = (i < IN_DIM) ? x[(size_t)row * IN_DIM + i] : -1.0f;
        pr[j] = fminf(fmaxf(__fmul_rn(xv, 0.1f), 0.0f), 1.0f);
    }

    for (int t = wid; t < T; t += 8) {
        const float* np = noise + ((size_t)t * B + row) * IN_DIM;
        float nv[NJ];
#pragma unroll
        for (int j = 0; j < NJ; j++) {
            int i = j * 32 + lane;
            nv[j] = (i < IN_DIM) ? np[i] : 2.0f;   // 2.0 < pr is always false
        }
        unsigned myw = 0;
#pragma unroll
        for (int j = 0; j < NJ; j++) {
            unsigned m = __ballot_sync(0xffffffffu, nv[j] < pr[j]);
            if (lane == j) myw = m;
        }
        if (lane < NJ)
            g_masks[((size_t)t * B + row) * NJ + lane] = myw;
    }
}

// ---------------------------------------------------------------------------
// Pass 2: LIF recurrence. Cluster of 2 CTAs splits H=128; W1 half in smem.
// T-loop consumes only the L2-resident mask words (no noise traffic).
// ---------------------------------------------------------------------------
__global__ void __launch_bounds__(NTHREADS, 1)
snn_cluster_kernel(const float* __restrict__ W1,
                   const float* __restrict__ b1,
                   const float* __restrict__ W2,
                   const float* __restrict__ b2,
                   float* __restrict__ out,
                   int B, int T)
{
    extern __shared__ float smem[];
    float*    W1s = smem;                                  // [784][64]
    float*    W2s = smem + IN_DIM * HH;                    // [128][10]
    unsigned* spb = (unsigned*)(W2s + H_DIM * OUT_DIM);    // [2 parity][28 rows][2 words]

    cg::cluster_group cluster = cg::this_cluster();
    const int rank = (int)cluster.block_rank();            // 0 or 1
    const unsigned* rspb =
        (const unsigned*)cluster.map_shared_rank((void*)spb, rank ^ 1);

    const int tid  = threadIdx.x;
    const int wid  = tid >> 5;
    const int lane = tid & 31;
    const int cid  = blockIdx.x >> 1;

    // Stage W1 half + W2 into shared (read from HBM once per CTA)
    for (int idx = tid; idx < IN_DIM * HH; idx += NTHREADS) {
        int i = idx >> 6;
        int c = idx & 63;
        W1s[idx] = W1[i * H_DIM + rank * HH + c];
    }
    for (int idx = tid; idx < H_DIM * OUT_DIM; idx += NTHREADS)
        W2s[idx] = W2[idx];
    __syncthreads();

    const float b1c0 = b1[rank * HH + 2 * lane];
    const float b1c1 = b1[rank * HH + 2 * lane + 1];
    const float b2v  = (lane < OUT_DIM) ? b2[lane] : 0.0f;

    const int row0 = cid * ROWS_PER_CLUSTER + wid;
    const int row1 = row0 + NWARP;
    const bool v0 = (row0 < B);
    const bool v1 = (row1 < B);

    float mA0 = 0.0f, mA1 = 0.0f;
    float mB0 = 0.0f, mB1 = 0.0f;
    float mem2a = 0.0f, mem2b = 0.0f;
    float cnta = 0.0f, cntb = 0.0f;

    // Layer-1 step: mask-driven sparse W1 gather + LIF + spike-ballot publish.
    auto layer1_row = [&](float& m0, float& m1, int row, int rl, int par, int t) {
        const unsigned* mp = g_masks + ((size_t)t * B + row) * NJ;
        unsigned mw[NJ];
#pragma unroll
        for (int j = 0; j < NJ; j++) mw[j] = mp[j];   // uniform, batched (L2 hits)

        float a0 = 0.0f, a1 = 0.0f;
#pragma unroll
        for (int j = 0; j < NJ; j++) {
            unsigned m = mw[j];
            const float* base = W1s + (j * 32 << 6) + (lane << 1);
            while (m) {
                int bb = __ffs(m) - 1; m &= (m - 1);
                float2 w = *(const float2*)(base + (bb << 6));
                a0 = __fadd_rn(a0, w.x);
                a1 = __fadd_rn(a1, w.y);
            }
        }
        m0 = __fadd_rn(__fadd_rn(__fmul_rn(BETA_F, m0), a0), b1c0);
        m1 = __fadd_rn(__fadd_rn(__fmul_rn(BETA_F, m1), a1), b1c1);
        bool s0 = (m0 >= 1.0f);
        bool s1 = (m1 >= 1.0f);
        if (s0) m0 = 0.0f;
        if (s1) m1 = 0.0f;
        unsigned e = __ballot_sync(0xffffffffu, s0);  // bit l -> local h = 2l
        unsigned o = __ballot_sync(0xffffffffu, s1);  // bit l -> local h = 2l+1
        if (lane == 0) {
            spb[(par * ROWS_PER_CLUSTER + rl) * 2 + 0] = e;
            spb[(par * ROWS_PER_CLUSTER + rl) * 2 + 1] = o;
        }
    };

    // Layer-2 step (rank 0 only, lanes 0..9): gather sp1 halves, LIF, count.
    auto layer2_row = [&](float& m2, float& cnt, int rl, int par) {
        unsigned e0 = spb [(par * ROWS_PER_CLUSTER + rl) * 2 + 0];
        unsigned o0 = spb [(par * ROWS_PER_CLUSTER + rl) * 2 + 1];
        unsigned e1 = rspb[(par * ROWS_PER_CLUSTER + rl) * 2 + 0];
        unsigned o1 = rspb[(par * ROWS_PER_CLUSTER + rl) * 2 + 1];
        float s2 = 0.0f;
        unsigned m;
        m = e0; while (m) { int h =      2*(__ffs(m)-1);     m &= m-1; s2 = __fadd_rn(s2, W2s[h*OUT_DIM + lane]); }
        m = o0; while (m) { int h =      2*(__ffs(m)-1) + 1; m &= m-1; s2 = __fadd_rn(s2, W2s[h*OUT_DIM + lane]); }
        m = e1; while (m) { int h = 64 + 2*(__ffs(m)-1);     m &= m-1; s2 = __fadd_rn(s2, W2s[h*OUT_DIM + lane]); }
        m = o1; while (m) { int h = 64 + 2*(__ffs(m)-1) + 1; m &= m-1; s2 = __fadd_rn(s2, W2s[h*OUT_DIM + lane]); }
        m2 = __fadd_rn(__fadd_rn(__fmul_rn(BETA_F, m2), s2), b2v);
        if (m2 >= 1.0f) { cnt = __fadd_rn(cnt, 1.0f); m2 = 0.0f; }
    };

    for (int t = 0; t < T; t++) {
        const int par = t & 1;
        if (v0) layer1_row(mA0, mA1, row0, wid,         par, t);
        if (v1) layer1_row(mB0, mB1, row1, wid + NWARP, par, t);

        cluster.sync();   // publish sp1 halves across the pair (double-buffered)

        if (rank == 0 && lane < OUT_DIM) {
            if (v0) layer2_row(mem2a, cnta, wid,         par);
            if (v1) layer2_row(mem2b, cntb, wid + NWARP, par);
        }
    }

    if (rank == 0 && lane < OUT_DIM) {
        if (v0) out[(size_t)row0 * OUT_DIM + lane] = cnta;
        if (v1) out[(size_t)row1 * OUT_DIM + lane] = cntb;
    }

    // No CTA may exit while its peer can still read this CTA's SMEM via DSMEM.
    cluster.sync();
}

extern "C" void kernel_launch(void* const* d_in, const int* in_sizes, int n_in,
                              void* d_out, int out_size) {
    const float* x     = (const float*)d_in[0];
    const float* noise = (const float*)d_in[1];
    const float* W1    = (const float*)d_in[2];
    const float* b1    = (const float*)d_in[3];
    const float* W2    = (const float*)d_in[4];
    const float* b2    = (const float*)d_in[5];
    float* out = (float*)d_out;

    const int B = in_sizes[0] / IN_DIM;                                    // 2048
    const int T = (int)((long long)in_sizes[1] / ((long long)B * IN_DIM)); // 100

    // Pass 1: Poisson encoding -> bitmasks (fully parallel, DRAM-bound)
    snn_encode_kernel<<<B, 256>>>(x, noise, B, T);

    // Pass 2: LIF recurrence over L2-resident masks
    const int numClusters = (B + ROWS_PER_CLUSTER - 1) / ROWS_PER_CLUSTER;  // 74

    cudaFuncSetAttribute(snn_cluster_kernel,
                         cudaFuncAttributeMaxDynamicSharedMemorySize,
                         (int)SMEM_BYTES);

    cudaLaunchConfig_t cfg = {};
    cfg.gridDim  = dim3(2 * numClusters, 1, 1);  // 148 CTAs = 74 clusters, one wave
    cfg.blockDim = dim3(NTHREADS, 1, 1);
    cfg.dynamicSmemBytes = SMEM_BYTES;
    cfg.stream = 0;

    cudaLaunchAttribute attrs[1];
    attrs[0].id = cudaLaunchAttributeClusterDimension;
    attrs[0].val.clusterDim.x = 2;
    attrs[0].val.clusterDim.y = 1;
    attrs[0].val.clusterDim.z = 1;
    cfg.attrs = attrs;
    cfg.numAttrs = 1;

    cudaLaunchKernelEx(&cfg, snn_cluster_kernel, W1, b1, W2, b2, out, B, T);
}

// round 17
// speedup vs baseline: 1.1917x; 1.1901x over previous
#include <cuda_runtime.h>
#include <cuda_bf16.h>
#include <cstdint>
#include <cstddef>

// Problem constants (reference: B=2048, IN=784, H=128, OUT=10, T=100)
#define IN_DIM   784
#define H_DIM    128
#define HH        64      // hidden columns per gather CTA (H split in 2 halves)
#define OUT_DIM   10
#define BETA_F   0.9f
#define NJ        25      // ceil(784/32)

#define MAXB 2048
#define MAXT 100

// Scratch (static __device__ — no runtime allocation).
// Spike bitmasks: [T*B][NJ], bit b of word j = spike at input i = j*32+b.
__device__ unsigned g_masks[(size_t)MAXT * MAXB * NJ];            // 20.5 MB
// Layer-1 dots: C1[t*B+b][h] = s_t[b] @ W1[:,h]  (exact in-order fp32 sum)
__device__ float    g_c1[(size_t)MAXT * MAXB * H_DIM];            // 105 MB

#define GATHER_THREADS 512
#define GATHER_SMEM (IN_DIM * HH * sizeof(float))   // 200704 B

// ---------------------------------------------------------------------------
// Pass 1: Poisson encoding. One CTA per batch row; warp w handles t = w, w+8,…
// Reads 642 MB noise once, writes ballot masks.
// ---------------------------------------------------------------------------
__global__ void __launch_bounds__(256, 8)
snn_encode_kernel(const float* __restrict__ x,
                  const float* __restrict__ noise,
                  int B, int T)
{
    const int row  = blockIdx.x;
    const int wid  = threadIdx.x >> 5;
    const int lane = threadIdx.x & 31;

    // Per-lane spike probabilities (fp32-exact vs reference: clip(x*0.1, 0, 1))
    float pr[NJ];
#pragma unroll
    for (int j = 0; j < NJ; j++) {
        int i = j * 32 + lane;
        float xv = (i < IN_DIM) ? x[(size_t)row * IN_DIM + i] : -1.0f;
        pr[j] = fminf(fmaxf(__fmul_rn(xv, 0.1f), 0.0f), 1.0f);
    }

    for (int t = wid; t < T; t += 8) {
        const float* np = noise + ((size_t)t * B + row) * IN_DIM;
        float nv[NJ];
#pragma unroll
        for (int j = 0; j < NJ; j++) {
            int i = j * 32 + lane;
            nv[j] = (i < IN_DIM) ? np[i] : 2.0f;   // 2.0 < pr is always false
        }
        unsigned myw = 0;
#pragma unroll
        for (int j = 0; j < NJ; j++) {
            unsigned m = __ballot_sync(0xffffffffu, nv[j] < pr[j]);
            if (lane == j) myw = m;
        }
        if (lane < NJ)
            g_masks[((size_t)t * B + row) * NJ + lane] = myw;
    }
}

// ---------------------------------------------------------------------------
// Pass 2: parallel sparse gather. C1[t][b][:] = s_t[b] @ W1, all (t,b) tasks
// independent. 148 CTAs (1/SM); CTA holds one 64-col half of W1 in smem.
// No barriers after staging — warps free-run over their task lists.
// Bit-walk is in increasing input order => rounding identical to reference.
// ---------------------------------------------------------------------------
__global__ void __launch_bounds__(GATHER_THREADS, 1)
snn_gather_kernel(const float* __restrict__ W1, int B, int T)
{
    extern __shared__ float W1s[];                 // [784][64]
    const int rank = blockIdx.x & 1;               // which 64-col half
    const int cih  = blockIdx.x >> 1;              // CTA index within half
    const int tid  = threadIdx.x;
    const int wid  = tid >> 5;
    const int lane = tid & 31;

    // Stage W1 half into shared
    for (int idx = tid; idx < IN_DIM * HH; idx += GATHER_THREADS) {
        int i = idx >> 6;
        int c = idx & 63;
        W1s[idx] = W1[i * H_DIM + rank * HH + c];
    }
    __syncthreads();

    const int warpsPerHalf = (gridDim.x >> 1) * (GATHER_THREADS / 32);
    const int w  = cih * (GATHER_THREADS / 32) + wid;
    const int TB = T * B;

    for (int p = w; p < TB; p += warpsPerHalf) {
        const unsigned* mp = g_masks + (size_t)p * NJ;
        unsigned mw[NJ];
#pragma unroll
        for (int j = 0; j < NJ; j++) mw[j] = mp[j];   // uniform, batched

        float a0 = 0.0f, a1 = 0.0f;
#pragma unroll
        for (int j = 0; j < NJ; j++) {
            unsigned m = mw[j];
            const float* base = W1s + (j << 11) + (lane << 1);  // j*32 rows * 64
            while (m) {
                int bb = __ffs(m) - 1; m &= (m - 1);
                float2 wv = *(const float2*)(base + (bb << 6));
                a0 = __fadd_rn(a0, wv.x);
                a1 = __fadd_rn(a1, wv.y);
            }
        }
        float2 o; o.x = a0; o.y = a1;
        // lane l -> cols rank*64 + 2l, 2l+1 ; warp writes 256B contiguous
        ((float2*)(g_c1 + (size_t)p * H_DIM + rank * HH))[lane] = o;
    }
}

// ---------------------------------------------------------------------------
// Pass 3: LIF recurrence. One warp per batch row; lane covers h = lane + 32k.
// Fully independent warps — zero block/cluster synchronization.
// ---------------------------------------------------------------------------
__global__ void __launch_bounds__(256)
snn_recur_kernel(const float* __restrict__ b1,
                 const float* __restrict__ W2,
                 const float* __restrict__ b2,
                 float* __restrict__ out,
                 int B, int T)
{
    __shared__ float W2s[H_DIM * OUT_DIM];          // 5 KB
    const int tid  = threadIdx.x;
    const int wid  = tid >> 5;
    const int lane = tid & 31;

    for (int idx = tid; idx < H_DIM * OUT_DIM; idx += 256)
        W2s[idx] = W2[idx];
    __syncthreads();

    const int b = blockIdx.x * 8 + wid;
    if (b >= B) return;                              // uniform per warp

    float b1v[4];
#pragma unroll
    for (int k = 0; k < 4; k++) b1v[k] = b1[lane + 32 * k];
    const float b2v = (lane < OUT_DIM) ? b2[lane] : 0.0f;

    float m1[4] = {0.0f, 0.0f, 0.0f, 0.0f};
    float m2 = 0.0f, cnt = 0.0f;

    const size_t strideT = (size_t)B * H_DIM;
    const float* cp = g_c1 + (size_t)b * H_DIM;

    // software prefetch of C1 row for t+1
    float c[4], cn[4];
#pragma unroll
    for (int k = 0; k < 4; k++) c[k] = cp[lane + 32 * k];

    for (int t = 0; t < T; t++) {
        if (t + 1 < T) {
            const float* np = cp + (size_t)(t + 1) * strideT;
#pragma unroll
            for (int k = 0; k < 4; k++) cn[k] = np[lane + 32 * k];
        }

        // LIF layer 1 (elementwise; op order matches reference exactly)
        unsigned sw[4];
#pragma unroll
        for (int k = 0; k < 4; k++) {
            float m = __fadd_rn(__fadd_rn(__fmul_rn(BETA_F, m1[k]), c[k]), b1v[k]);
            bool s = (m >= 1.0f);
            if (s) m = 0.0f;
            m1[k] = m;
            sw[k] = __ballot_sync(0xffffffffu, s);   // bit l <-> h = 32k + l
        }

        // LIF layer 2: lanes 0..9 walk hidden-spike bits in ascending h order
        if (lane < OUT_DIM) {
            float s2 = 0.0f;
#pragma unroll
            for (int k = 0; k < 4; k++) {
                unsigned m = sw[k];
                while (m) {
                    int l = __ffs(m) - 1; m &= (m - 1);
                    s2 = __fadd_rn(s2, W2s[(32 * k + l) * OUT_DIM + lane]);
                }
            }
            m2 = __fadd_rn(__fadd_rn(__fmul_rn(BETA_F, m2), s2), b2v);
            if (m2 >= 1.0f) { cnt = __fadd_rn(cnt, 1.0f); m2 = 0.0f; }
        }

#pragma unroll
        for (int k = 0; k < 4; k++) c[k] = cn[k];
    }

    if (lane < OUT_DIM)
        out[(size_t)b * OUT_DIM + lane] = cnt;
}

extern "C" void kernel_launch(void* const* d_in, const int* in_sizes, int n_in,
                              void* d_out, int out_size) {
    const float* x     = (const float*)d_in[0];
    const float* noise = (const float*)d_in[1];
    const float* W1    = (const float*)d_in[2];
    const float* b1    = (const float*)d_in[3];
    const float* W2    = (const float*)d_in[4];
    const float* b2    = (const float*)d_in[5];
    float* out = (float*)d_out;

    const int B = in_sizes[0] / IN_DIM;                                    // 2048
    const int T = (int)((long long)in_sizes[1] / ((long long)B * IN_DIM)); // 100

    // Pass 1: Poisson encoding -> bitmasks (DRAM-bound, fully parallel)
    snn_encode_kernel<<<B, 256>>>(x, noise, B, T);

    // Pass 2: parallel sparse W1 gather -> C1 dots (issue/smem-bound)
    cudaFuncSetAttribute(snn_gather_kernel,
                         cudaFuncAttributeMaxDynamicSharedMemorySize,
                         (int)GATHER_SMEM);
    snn_gather_kernel<<<148, GATHER_THREADS, GATHER_SMEM>>>(W1, B, T);

    // Pass 3: LIF recurrence (1 warp/row, no syncs)
    snn_recur_kernel<<<(B + 7) / 8, 256>>>(b1, W2, b2, out, B, T);
}